// round 1
// baseline (speedup 1.0000x reference)
#include <cuda_runtime.h>
#include <cstdint>

#define BB 16
#define NN 1024
#define DD 64
#define NHH 4
#define HDD 16
#define HH 256
#define WW 256

// ---------------- scratch (device globals: no runtime allocation) ----------
__device__ float g_Q[BB*NHH*NN*HDD];     // (b,h,n,j) 4MB
__device__ float g_K[BB*NHH*NN*HDD];     // 4MB
__device__ float g_V[BB*NHH*NN*HDD];     // 4MB
__device__ float g_att[BB*NN*DD];        // pose-scaled attention out 4MB
__device__ float g_pose[BB*DD];          // 1 + pose_mod

// ---------------- f32x2 packed helpers (sm_10x) -----------------------------
__device__ __forceinline__ unsigned long long pack2(float lo, float hi) {
    unsigned long long r;
    asm("mov.b64 %0, {%1,%2};" : "=l"(r) : "f"(lo), "f"(hi));
    return r;
}
__device__ __forceinline__ void unpack2(unsigned long long v, float& lo, float& hi) {
    asm("mov.b64 {%0,%1}, %2;" : "=f"(lo), "=f"(hi) : "l"(v));
}
__device__ __forceinline__ unsigned long long ffma2(unsigned long long a,
                                                    unsigned long long b,
                                                    unsigned long long c) {
    unsigned long long d;
    asm("fma.rn.f32x2 %0, %1, %2, %3;" : "=l"(d) : "l"(a), "l"(b), "l"(c));
    return d;
}

// ---------------- K0: pose_scale[b][d] = 1 + pose_embed@Wp + bp -------------
__global__ void pose_kernel(const float* __restrict__ pe,
                            const float* __restrict__ Wp,
                            const float* __restrict__ bp) {
    int b = blockIdx.x, d = threadIdx.x;
    float s = bp[d];
    #pragma unroll 8
    for (int p = 0; p < 64; p++) s += pe[b*64 + p] * Wp[p*64 + d];
    g_pose[b*64 + d] = 1.0f + s;
}

// ---------------- K1: patch-mean gather + Q/K/V projection ------------------
// 32 points per block, 256 threads. Warp = one point (lanes = channels) so
// coords-dependent control flow is warp-uniform.
__global__ __launch_bounds__(256) void gather_project_kernel(
    const float* __restrict__ desc, const float* __restrict__ feat,
    const int*   __restrict__ coords,
    const float* __restrict__ Wq, const float* __restrict__ bq,
    const float* __restrict__ Wk, const float* __restrict__ bk,
    const float* __restrict__ Wv, const float* __restrict__ bv)
{
    __shared__ float pf[32][64];     // patch means
    __shared__ float dsc[32][64];    // desc tile
    __shared__ int sy[32], sx[32];

    int t = threadIdx.x;
    int gp0 = blockIdx.x * 32;           // global point index base (b*N+n linear)
    int b   = gp0 >> 10;                 // / N
    int n0  = gp0 & 1023;

    if (t < 32) {
        sy[t] = coords[(gp0 + t)*2 + 0];
        sx[t] = coords[(gp0 + t)*2 + 1];
    }
    #pragma unroll
    for (int i = 0; i < 8; i++) {
        int o = t + 256*i;
        ((float*)dsc)[o] = desc[(size_t)gp0*64 + o];
    }
    __syncthreads();

    int w = t >> 5, l = t & 31;
    for (int i = 0; i < 4; i++) {
        int p = w*4 + i;
        int y = sy[p], x = sx[p];
        int s = x - 2;
        bool fast = (s >= 0) && (s <= 248);    // both float4 loads in-row
        #pragma unroll
        for (int cp = 0; cp < 2; cp++) {
            int ch = l + 32*cp;
            const float* plane = feat + ((size_t)(b*64 + ch) << 16);
            float sum = 0.0f;
            if (fast) {
                int a = s & ~3;
                int o = s - a;                 // 0..3, warp-uniform
                #pragma unroll
                for (int dy = 0; dy < 5; dy++) {
                    int yy = y + dy - 2;
                    if (yy >= 0 && yy < HH) {
                        const float4* row = (const float4*)(plane + yy*WW + a);
                        float4 r0 = __ldg(row);
                        float4 r1 = __ldg(row + 1);
                        float v0=r0.x, v1=r0.y, v2=r0.z, v3=r0.w;
                        float v4=r1.x, v5=r1.y, v6=r1.z, v7=r1.w;
                        float rs;
                        switch (o) {
                            case 0:  rs = v0+v1+v2+v3+v4; break;
                            case 1:  rs = v1+v2+v3+v4+v5; break;
                            case 2:  rs = v2+v3+v4+v5+v6; break;
                            default: rs = v3+v4+v5+v6+v7; break;
                        }
                        sum += rs;
                    }
                }
            } else {
                // border in x: scalar with per-element bounds (zero padding)
                for (int dy = 0; dy < 5; dy++) {
                    int yy = y + dy - 2;
                    if (yy < 0 || yy >= HH) continue;
                    const float* row = plane + yy*WW;
                    #pragma unroll
                    for (int dx = 0; dx < 5; dx++) {
                        int xx = x + dx - 2;
                        if (xx >= 0 && xx < WW) sum += __ldg(row + xx);
                    }
                }
            }
            pf[p][ch] = sum * 0.04f;   // /25
        }
    }
    __syncthreads();

    // projection: thread owns column c = t&63 over points p = (t>>6)+4i
    int c = t & 63;
    int pbase = t >> 6;
    float accq[8], acck[8], accv[8];
    float bqc = bq[c], bkc = bk[c], bvc = bv[c];
    #pragma unroll
    for (int i = 0; i < 8; i++) { accq[i]=bqc; acck[i]=bkc; accv[i]=bvc; }
    for (int k = 0; k < 64; k++) {
        float wq = __ldg(Wq + k*64 + c);
        float wk = __ldg(Wk + k*64 + c);
        float wv = __ldg(Wv + k*64 + c);
        #pragma unroll
        for (int i = 0; i < 8; i++) {
            int p = pbase + 4*i;
            float dv = dsc[p][k];
            float pv = pf[p][k];
            accq[i] += dv * wq;
            acck[i] += pv * wk;
            accv[i] += pv * wv;
        }
    }
    int h = c >> 4, j = c & 15;
    size_t base = (size_t)(b*NHH + h) * NN;
    #pragma unroll
    for (int i = 0; i < 8; i++) {
        int p = pbase + 4*i;
        size_t idx = (base + n0 + p) * HDD + j;
        g_Q[idx] = accq[i];
        g_K[idx] = acck[i];
        g_V[idx] = accv[i];
    }
}

// ---------------- K2: attention per (b,h), 256 queries/block ----------------
// scores are bounded (|s| < ~2) -> no max subtraction needed. f32x2 math.
extern __shared__ float sm_attn[];
__global__ __launch_bounds__(256) void attn_kernel() {
    float* Ks = sm_attn;
    float* Vs = sm_attn + NN*HDD;

    int t = threadIdx.x;
    int b = blockIdx.z, h = blockIdx.y;
    size_t bh = (size_t)(b*NHH + h) * NN * HDD;

    const float4* Kg = (const float4*)(g_K + bh);
    const float4* Vg = (const float4*)(g_V + bh);
    float4* Ks4 = (float4*)Ks;
    float4* Vs4 = (float4*)Vs;
    #pragma unroll
    for (int i = 0; i < 16; i++) {
        Ks4[t + 256*i] = Kg[t + 256*i];
        Vs4[t + 256*i] = Vg[t + 256*i];
    }

    int n = blockIdx.x*256 + t;
    const ulonglong2* qp = (const ulonglong2*)(g_Q + bh + (size_t)n*HDD);
    ulonglong2 qa = qp[0], qb = qp[1], qc = qp[2], qd = qp[3];
    __syncthreads();

    unsigned long long o0=0ull,o1=0ull,o2=0ull,o3=0ull,o4=0ull,o5=0ull,o6=0ull,o7=0ull;
    float lsum = 0.0f;

    #pragma unroll 2
    for (int kk = 0; kk < NN; kk++) {
        const ulonglong2* kr = (const ulonglong2*)(Ks + kk*HDD);
        ulonglong2 ka = kr[0], kb = kr[1], kc = kr[2], kd = kr[3];
        // two independent chains for ILP
        unsigned long long accA = 0ull, accB = 0ull;
        accA = ffma2(qa.x, ka.x, accA);  accB = ffma2(qa.y, ka.y, accB);
        accA = ffma2(qb.x, kb.x, accA);  accB = ffma2(qb.y, kb.y, accB);
        accA = ffma2(qc.x, kc.x, accA);  accB = ffma2(qc.y, kc.y, accB);
        accA = ffma2(qd.x, kd.x, accA);  accB = ffma2(qd.y, kd.y, accB);
        float a0,a1,b0,b1;
        unpack2(accA, a0, a1);
        unpack2(accB, b0, b1);
        float e = __expf(((a0+a1)+(b0+b1)) * 0.25f);
        lsum += e;
        unsigned long long e2 = pack2(e, e);
        const ulonglong2* vr = (const ulonglong2*)(Vs + kk*HDD);
        ulonglong2 va = vr[0], vb = vr[1], vc = vr[2], vd = vr[3];
        o0 = ffma2(e2, va.x, o0);  o1 = ffma2(e2, va.y, o1);
        o2 = ffma2(e2, vb.x, o2);  o3 = ffma2(e2, vb.y, o3);
        o4 = ffma2(e2, vc.x, o4);  o5 = ffma2(e2, vc.y, o5);
        o6 = ffma2(e2, vd.x, o6);  o7 = ffma2(e2, vd.y, o7);
    }

    float inv = 1.0f / lsum;
    float oo[16];
    unpack2(o0, oo[0],  oo[1]);  unpack2(o1, oo[2],  oo[3]);
    unpack2(o2, oo[4],  oo[5]);  unpack2(o3, oo[6],  oo[7]);
    unpack2(o4, oo[8],  oo[9]);  unpack2(o5, oo[10], oo[11]);
    unpack2(o6, oo[12], oo[13]); unpack2(o7, oo[14], oo[15]);

    const float* ps = g_pose + b*64 + h*16;
    float* outp = g_att + ((size_t)b*NN + n)*DD + h*16;
    #pragma unroll
    for (int j = 0; j < 16; j++) outp[j] = oo[j] * inv * ps[j];
}

// ---------------- K3: out = g_att @ Wo + bo ---------------------------------
__global__ __launch_bounds__(256) void outproj_kernel(const float* __restrict__ Wo,
                                                      const float* __restrict__ bo,
                                                      float* __restrict__ out) {
    __shared__ float fat[64*64];
    int t = threadIdx.x;
    size_t rbase = (size_t)blockIdx.x * 64;   // global row (b*N+n)
    #pragma unroll
    for (int i = 0; i < 16; i++) fat[t + 256*i] = g_att[rbase*64 + t + 256*i];
    __syncthreads();

    int c = t & 63, r0 = t >> 6;
    float acc[16];
    float bc = bo[c];
    #pragma unroll
    for (int i = 0; i < 16; i++) acc[i] = bc;
    for (int k = 0; k < 64; k++) {
        float wv = __ldg(Wo + k*64 + c);
        #pragma unroll
        for (int i = 0; i < 16; i++) acc[i] += fat[(r0 + 4*i)*64 + k] * wv;
    }
    #pragma unroll
    for (int i = 0; i < 16; i++) out[(rbase + r0 + 4*i)*64 + c] = acc[i];
}

// ---------------- launch ----------------------------------------------------
extern "C" void kernel_launch(void* const* d_in, const int* in_sizes, int n_in,
                              void* d_out, int out_size) {
    const float* desc   = (const float*)d_in[0];
    const float* feat   = (const float*)d_in[1];
    const int*   coords = (const int*)  d_in[2];
    const float* pose   = (const float*)d_in[3];
    const float* Wq = (const float*)d_in[4];  const float* bq = (const float*)d_in[5];
    const float* Wk = (const float*)d_in[6];  const float* bk = (const float*)d_in[7];
    const float* Wv = (const float*)d_in[8];  const float* bv = (const float*)d_in[9];
    const float* Wp = (const float*)d_in[10]; const float* bp = (const float*)d_in[11];
    const float* Wo = (const float*)d_in[12]; const float* bo = (const float*)d_in[13];
    float* out = (float*)d_out;

    cudaFuncSetAttribute(attn_kernel, cudaFuncAttributeMaxDynamicSharedMemorySize,
                         2 * NN * HDD * sizeof(float));

    pose_kernel<<<BB, DD>>>(pose, Wp, bp);
    gather_project_kernel<<<(BB*NN)/32, 256>>>(desc, feat, coords,
                                               Wq, bq, Wk, bk, Wv, bv);
    attn_kernel<<<dim3(NN/256, NHH, BB), 256, 2*NN*HDD*sizeof(float)>>>();
    outproj_kernel<<<(BB*NN)/64, 256>>>(Wo, bo, out);
}

// round 2
// speedup vs baseline: 1.1392x; 1.1392x over previous
#include <cuda_runtime.h>
#include <cstdint>

#define BB 16
#define NN 1024
#define DD 64
#define NHH 4
#define HDD 16
#define HH 256
#define WW 256

// ---------------- scratch (device globals: no runtime allocation) ----------
__device__ float g_Q[BB*NHH*NN*HDD];     // (b,h,n,j) 4MB
__device__ float g_K[BB*NHH*NN*HDD];     // 4MB
__device__ float g_V[BB*NHH*NN*HDD];     // 4MB
__device__ float g_att[BB*NN*DD];        // pose-scaled attention out 4MB
__device__ float g_pose[BB*DD];          // 1 + pose_mod

// ---------------- f32x2 packed helpers (sm_10x) -----------------------------
__device__ __forceinline__ unsigned long long pack2(float lo, float hi) {
    unsigned long long r;
    asm("mov.b64 %0, {%1,%2};" : "=l"(r) : "f"(lo), "f"(hi));
    return r;
}
__device__ __forceinline__ void unpack2(unsigned long long v, float& lo, float& hi) {
    asm("mov.b64 {%0,%1}, %2;" : "=f"(lo), "=f"(hi) : "l"(v));
}
__device__ __forceinline__ unsigned long long ffma2(unsigned long long a,
                                                    unsigned long long b,
                                                    unsigned long long c) {
    unsigned long long d;
    asm("fma.rn.f32x2 %0, %1, %2, %3;" : "=l"(d) : "l"(a), "l"(b), "l"(c));
    return d;
}
__device__ __forceinline__ float ex2f(float x) {
    float y;
    asm("ex2.approx.f32 %0, %1;" : "=f"(y) : "f"(x));
    return y;
}

// ---------------- K1: patch-mean gather + Q/K/V projection (+pose tail) -----
// Blocks [0,512): 32 points per block, 256 threads. Warp = one point
// (lanes = channels) so coords-dependent control flow is warp-uniform.
// Blocks [512,528): pose_scale[b][d] = 1 + pose_embed@Wp + bp  (64 threads).
__global__ __launch_bounds__(256) void gather_project_kernel(
    const float* __restrict__ desc, const float* __restrict__ feat,
    const int*   __restrict__ coords,
    const float* __restrict__ Wq, const float* __restrict__ bq,
    const float* __restrict__ Wk, const float* __restrict__ bk,
    const float* __restrict__ Wv, const float* __restrict__ bv,
    const float* __restrict__ pe, const float* __restrict__ Wp,
    const float* __restrict__ bp)
{
    if (blockIdx.x >= 512) {            // ---- pose tail blocks ----
        int b = blockIdx.x - 512;
        int d = threadIdx.x;
        if (d < 64) {
            float s = bp[d];
            #pragma unroll 8
            for (int p = 0; p < 64; p++) s += pe[b*64 + p] * Wp[p*64 + d];
            g_pose[b*64 + d] = 1.0f + s;
        }
        return;
    }

    __shared__ float pf[32][64];     // patch means
    __shared__ float dsc[32][64];    // desc tile
    __shared__ int sy[32], sx[32];

    int t = threadIdx.x;
    int gp0 = blockIdx.x * 32;           // global point index base (b*N+n linear)
    int b   = gp0 >> 10;                 // / N
    int n0  = gp0 & 1023;

    if (t < 32) {
        sy[t] = coords[(gp0 + t)*2 + 0];
        sx[t] = coords[(gp0 + t)*2 + 1];
    }
    #pragma unroll
    for (int i = 0; i < 8; i++) {
        int o = t + 256*i;
        ((float*)dsc)[o] = desc[(size_t)gp0*64 + o];
    }
    __syncthreads();

    int w = t >> 5, l = t & 31;
    for (int i = 0; i < 4; i++) {
        int p = w*4 + i;
        int y = sy[p], x = sx[p];
        int s = x - 2;
        bool fast = (s >= 0) && (s <= 248);    // both float4 loads in-row
        if (fast) {
            int a = s & ~3;
            int o = s - a;                     // 0..3, warp-uniform
            #pragma unroll
            for (int cp = 0; cp < 2; cp++) {
                int ch = l + 32*cp;
                const float* plane = feat + ((size_t)(b*64 + ch) << 16);
                float sum = 0.0f;
                // clamp+mask so all 10 LDGs issue back-to-back (MLP)
                #pragma unroll
                for (int dy = 0; dy < 5; dy++) {
                    int yy = y + dy - 2;
                    int yc = min(max(yy, 0), HH-1);
                    float m = (yy == yc) ? 1.0f : 0.0f;
                    const float4* row = (const float4*)(plane + yc*WW + a);
                    float4 r0 = __ldg(row);
                    float4 r1 = __ldg(row + 1);
                    float v0=r0.x, v1=r0.y, v2=r0.z, v3=r0.w;
                    float v4=r1.x, v5=r1.y, v6=r1.z, v7=r1.w;
                    float rs;
                    switch (o) {
                        case 0:  rs = v0+v1+v2+v3+v4; break;
                        case 1:  rs = v1+v2+v3+v4+v5; break;
                        case 2:  rs = v2+v3+v4+v5+v6; break;
                        default: rs = v3+v4+v5+v6+v7; break;
                    }
                    sum = fmaf(m, rs, sum);
                }
                pf[p][ch] = sum * 0.04f;   // /25
            }
        } else {
            // border in x (~2.7% of warps): scalar with per-element bounds
            #pragma unroll
            for (int cp = 0; cp < 2; cp++) {
                int ch = l + 32*cp;
                const float* plane = feat + ((size_t)(b*64 + ch) << 16);
                float sum = 0.0f;
                for (int dy = 0; dy < 5; dy++) {
                    int yy = y + dy - 2;
                    if (yy < 0 || yy >= HH) continue;
                    const float* row = plane + yy*WW;
                    #pragma unroll
                    for (int dx = 0; dx < 5; dx++) {
                        int xx = x + dx - 2;
                        if (xx >= 0 && xx < WW) sum += __ldg(row + xx);
                    }
                }
                pf[p][ch] = sum * 0.04f;
            }
        }
    }
    __syncthreads();

    // projection: thread owns column c = t&63 over points p = (t>>6)+4i
    int c = t & 63;
    int pbase = t >> 6;
    float accq[8], acck[8], accv[8];
    float bqc = bq[c], bkc = bk[c], bvc = bv[c];
    #pragma unroll
    for (int i = 0; i < 8; i++) { accq[i]=bqc; acck[i]=bkc; accv[i]=bvc; }
    for (int k = 0; k < 64; k++) {
        float wq = __ldg(Wq + k*64 + c);
        float wk = __ldg(Wk + k*64 + c);
        float wv = __ldg(Wv + k*64 + c);
        #pragma unroll
        for (int i = 0; i < 8; i++) {
            int p = pbase + 4*i;
            float dv = dsc[p][k];
            float pv = pf[p][k];
            accq[i] += dv * wq;
            acck[i] += pv * wk;
            accv[i] += pv * wv;
        }
    }
    int h = c >> 4, j = c & 15;
    size_t base = (size_t)(b*NHH + h) * NN;
    #pragma unroll
    for (int i = 0; i < 8; i++) {
        int p = pbase + 4*i;
        size_t idx = (base + n0 + p) * HDD + j;
        g_Q[idx] = accq[i];
        g_K[idx] = acck[i];
        g_V[idx] = accv[i];
    }
}

// ---------------- K2: attention per (b,h), 512 queries/block ----------------
// grid (2, NH, B) = 128 blocks -> single wave on 148 SMs, 16 warps/SM.
// scores are bounded -> no max subtraction. Q pre-scaled by 0.25*log2(e),
// exp via raw ex2. f32x2 packed math, 2 keys per iteration.
extern __shared__ float sm_attn[];
__global__ __launch_bounds__(512) void attn_kernel() {
    float* Ks = sm_attn;
    float* Vs = sm_attn + NN*HDD;

    int t = threadIdx.x;
    int b = blockIdx.z, h = blockIdx.y;
    size_t bh = (size_t)(b*NHH + h) * NN * HDD;

    const float4* Kg = (const float4*)(g_K + bh);
    const float4* Vg = (const float4*)(g_V + bh);
    float4* Ks4 = (float4*)Ks;
    float4* Vs4 = (float4*)Vs;
    #pragma unroll
    for (int i = 0; i < 8; i++) {
        Ks4[t + 512*i] = Kg[t + 512*i];
        Vs4[t + 512*i] = Vg[t + 512*i];
    }

    int n = blockIdx.x*512 + t;
    const float4* qp = (const float4*)(g_Q + bh + (size_t)n*HDD);
    const float CSC = 0.25f * 1.4426950408889634f;   // 1/sqrt(hd) * log2(e)
    unsigned long long q[8];
    #pragma unroll
    for (int i = 0; i < 4; i++) {
        float4 qv = qp[i];
        q[2*i+0] = pack2(qv.x*CSC, qv.y*CSC);
        q[2*i+1] = pack2(qv.z*CSC, qv.w*CSC);
    }
    __syncthreads();

    unsigned long long o0=0ull,o1=0ull,o2=0ull,o3=0ull,o4=0ull,o5=0ull,o6=0ull,o7=0ull;
    float lsum = 0.0f;

    for (int kk = 0; kk < NN; kk += 2) {
        const ulonglong2* kr = (const ulonglong2*)(Ks + kk*HDD);
        ulonglong2 k0a = kr[0], k0b = kr[1], k0c = kr[2], k0d = kr[3];
        ulonglong2 k1a = kr[4], k1b = kr[5], k1c = kr[6], k1d = kr[7];

        unsigned long long aA = 0ull, aB = 0ull, bA = 0ull, bB = 0ull;
        aA = ffma2(q[0], k0a.x, aA);  aB = ffma2(q[1], k0a.y, aB);
        bA = ffma2(q[0], k1a.x, bA);  bB = ffma2(q[1], k1a.y, bB);
        aA = ffma2(q[2], k0b.x, aA);  aB = ffma2(q[3], k0b.y, aB);
        bA = ffma2(q[2], k1b.x, bA);  bB = ffma2(q[3], k1b.y, bB);
        aA = ffma2(q[4], k0c.x, aA);  aB = ffma2(q[5], k0c.y, aB);
        bA = ffma2(q[4], k1c.x, bA);  bB = ffma2(q[5], k1c.y, bB);
        aA = ffma2(q[6], k0d.x, aA);  aB = ffma2(q[7], k0d.y, aB);
        bA = ffma2(q[6], k1d.x, bA);  bB = ffma2(q[7], k1d.y, bB);

        float a0,a1,a2,a3,b0,b1,b2,b3;
        unpack2(aA, a0, a1);  unpack2(aB, a2, a3);
        unpack2(bA, b0, b1);  unpack2(bB, b2, b3);
        float e0 = ex2f((a0+a1)+(a2+a3));
        float e1 = ex2f((b0+b1)+(b2+b3));
        lsum += e0 + e1;
        unsigned long long e0p = pack2(e0, e0);
        unsigned long long e1p = pack2(e1, e1);

        const ulonglong2* vr = (const ulonglong2*)(Vs + kk*HDD);
        ulonglong2 v0a = vr[0], v0b = vr[1], v0c = vr[2], v0d = vr[3];
        ulonglong2 v1a = vr[4], v1b = vr[5], v1c = vr[6], v1d = vr[7];
        o0 = ffma2(e0p, v0a.x, o0);  o1 = ffma2(e0p, v0a.y, o1);
        o2 = ffma2(e0p, v0b.x, o2);  o3 = ffma2(e0p, v0b.y, o3);
        o4 = ffma2(e0p, v0c.x, o4);  o5 = ffma2(e0p, v0c.y, o5);
        o6 = ffma2(e0p, v0d.x, o6);  o7 = ffma2(e0p, v0d.y, o7);
        o0 = ffma2(e1p, v1a.x, o0);  o1 = ffma2(e1p, v1a.y, o1);
        o2 = ffma2(e1p, v1b.x, o2);  o3 = ffma2(e1p, v1b.y, o3);
        o4 = ffma2(e1p, v1c.x, o4);  o5 = ffma2(e1p, v1c.y, o5);
        o6 = ffma2(e1p, v1d.x, o6);  o7 = ffma2(e1p, v1d.y, o7);
    }

    float inv = 1.0f / lsum;
    float oo[16];
    unpack2(o0, oo[0],  oo[1]);  unpack2(o1, oo[2],  oo[3]);
    unpack2(o2, oo[4],  oo[5]);  unpack2(o3, oo[6],  oo[7]);
    unpack2(o4, oo[8],  oo[9]);  unpack2(o5, oo[10], oo[11]);
    unpack2(o6, oo[12], oo[13]); unpack2(o7, oo[14], oo[15]);

    const float* ps = g_pose + b*64 + h*16;
    float* outp = g_att + ((size_t)b*NN + n)*DD + h*16;
    #pragma unroll
    for (int j = 0; j < 16; j++) outp[j] = oo[j] * inv * ps[j];
}

// ---------------- K3: out = g_att @ Wo + bo ---------------------------------
__global__ __launch_bounds__(256) void outproj_kernel(const float* __restrict__ Wo,
                                                      const float* __restrict__ bo,
                                                      float* __restrict__ out) {
    __shared__ float fat[64*64];
    int t = threadIdx.x;
    size_t rbase = (size_t)blockIdx.x * 64;   // global row (b*N+n)
    const float4* src = (const float4*)(g_att + rbase*64);
    float4* dst = (float4*)fat;
    #pragma unroll
    for (int i = 0; i < 4; i++) dst[t + 256*i] = src[t + 256*i];
    __syncthreads();

    int c = t & 63, r0 = t >> 6;
    float acc[16];
    float bc = bo[c];
    #pragma unroll
    for (int i = 0; i < 16; i++) acc[i] = bc;
    #pragma unroll 4
    for (int k = 0; k < 64; k += 4) {
        float w0 = __ldg(Wo + (k+0)*64 + c);
        float w1 = __ldg(Wo + (k+1)*64 + c);
        float w2 = __ldg(Wo + (k+2)*64 + c);
        float w3 = __ldg(Wo + (k+3)*64 + c);
        #pragma unroll
        for (int i = 0; i < 16; i++) {
            float4 f = *(const float4*)&fat[(r0 + 4*i)*64 + k];
            acc[i] += f.x*w0 + f.y*w1 + f.z*w2 + f.w*w3;
        }
    }
    #pragma unroll
    for (int i = 0; i < 16; i++) out[(rbase + r0 + 4*i)*64 + c] = acc[i];
}

// ---------------- launch ----------------------------------------------------
extern "C" void kernel_launch(void* const* d_in, const int* in_sizes, int n_in,
                              void* d_out, int out_size) {
    const float* desc   = (const float*)d_in[0];
    const float* feat   = (const float*)d_in[1];
    const int*   coords = (const int*)  d_in[2];
    const float* pose   = (const float*)d_in[3];
    const float* Wq = (const float*)d_in[4];  const float* bq = (const float*)d_in[5];
    const float* Wk = (const float*)d_in[6];  const float* bk = (const float*)d_in[7];
    const float* Wv = (const float*)d_in[8];  const float* bv = (const float*)d_in[9];
    const float* Wp = (const float*)d_in[10]; const float* bp = (const float*)d_in[11];
    const float* Wo = (const float*)d_in[12]; const float* bo = (const float*)d_in[13];
    float* out = (float*)d_out;

    cudaFuncSetAttribute(attn_kernel, cudaFuncAttributeMaxDynamicSharedMemorySize,
                         2 * NN * HDD * sizeof(float));

    gather_project_kernel<<<512 + BB, 256>>>(desc, feat, coords,
                                             Wq, bq, Wk, bk, Wv, bv,
                                             pose, Wp, bp);
    attn_kernel<<<dim3(NN/512, NHH, BB), 512, 2*NN*HDD*sizeof(float)>>>();
    outproj_kernel<<<(BB*NN)/64, 256>>>(Wo, bo, out);
}